// round 15
// baseline (speedup 1.0000x reference)
#include <cuda_runtime.h>
#include <cuda_fp16.h>
#include <math.h>
#include <stdint.h>

// ============================================================================
// PaddedSHCSA, single-pass fp16 GEMMs, fused softmax (rel_err ~6e-4).
// Round 15: persistent CTAs (grid-stride over tiles) to kill wave quantization
// (scores was 1.78 waves, out 1.73). Tile order: tri / row-major / LPT.
// ============================================================================

#define S_DIM   4096
#define F_DIM   2048
#define F3_DIM  6144

__device__ __half g_xh [(size_t)S_DIM * F_DIM];
__device__ __half g_Wth[(size_t)F3_DIM * F_DIM];   // W^T hi [3F][F]
__device__ __half g_qh [(size_t)S_DIM * F_DIM];
__device__ __half g_kh [(size_t)S_DIM * F_DIM];
__device__ __half g_vTh[(size_t)F_DIM * S_DIM];    // v^T [F][S]
__device__ __half g_atth[(size_t)S_DIM * S_DIM];   // unnormalized exp
__device__ float  g_psum[(size_t)S_DIM * 32];      // per (row, n-block) sums
__device__ float  g_inv [S_DIM];                   // 1/rowsum (0 if padded)

// ---------------- low-level helpers -----------------------------------------
__device__ __forceinline__ uint32_t smem_u32(const void* p) {
    uint32_t a;
    asm("{ .reg .u64 t; cvta.to.shared.u64 t, %1; cvt.u32.u64 %0, t; }" : "=r"(a) : "l"(p));
    return a;
}
#define CP_ASYNC16(dst_u32, src_ptr) \
    asm volatile("cp.async.cg.shared.global [%0], [%1], 16;" :: "r"(dst_u32), "l"(src_ptr))
#define CP_COMMIT()  asm volatile("cp.async.commit_group;" ::: "memory")
#define CP_WAIT1()   asm volatile("cp.async.wait_group 1;" ::: "memory")
#define CP_WAIT0()   asm volatile("cp.async.wait_group 0;" ::: "memory")

__device__ __forceinline__ void ldsm_x4(uint32_t* r, uint32_t addr) {
    asm volatile("ldmatrix.sync.aligned.m8n8.x4.shared.b16 {%0,%1,%2,%3}, [%4];"
        : "=r"(r[0]), "=r"(r[1]), "=r"(r[2]), "=r"(r[3]) : "r"(addr));
}
__device__ __forceinline__ void mma16816(float* c, const uint32_t* a, const uint32_t* b) {
    asm volatile("mma.sync.aligned.m16n8k16.row.col.f32.f16.f16.f32 "
        "{%0,%1,%2,%3}, {%4,%5,%6,%7}, {%8,%9}, {%0,%1,%2,%3};"
        : "+f"(c[0]), "+f"(c[1]), "+f"(c[2]), "+f"(c[3])
        : "r"(a[0]), "r"(a[1]), "r"(a[2]), "r"(a[3]), "r"(b[0]), "r"(b[1]));
}

// ---------------- smem layout -----------------------------------------------
static constexpr int TILE_B = 128 * 128;             // 16384 B
static constexpr int STAGE_B = 2 * TILE_B;           // Ah Bh = 32768 B
static constexpr int NSTAGE = 3;
static constexpr int SMEM_BYTES = NSTAGE * STAGE_B;  // 98304 B (2 CTAs/SM)
static constexpr int PT = 136;                       // vT transpose staging pitch

// ============================================================================
// Persistent GEMM: 256 threads, 8 warps 2x4, warp tile 64x32, BK=64 swizzled,
// 3-stage ring. Grid-stride loop over tiles (ntiles passed in).
// MODE 0: qkv (bias; -> q/k hi rows, vT hi transposed); tiles row-major
// MODE 1: scores->att: exp(scale*s) masked -> att fp16 + psum; triangular
// MODE 2: out: (att@v)*inv[row]; tiles LPT (heavy by first)
// ============================================================================
template<int MODE>
__global__ __launch_bounds__(256, 2) void hmma_gemm(
    const __half* __restrict__ Ah, int lda,
    const __half* __restrict__ Bh, int ldb,
    int K, const float* __restrict__ bias, float scale,
    float* __restrict__ outf, int ldo,
    __half* __restrict__ qh, __half* __restrict__ kh,
    __half* __restrict__ vTh,
    int F, int S, const int* __restrict__ np_ptr,
    int ntiles, int nbx)
{
    extern __shared__ __align__(128) char smem[];
    const uint32_t sbase = smem_u32(smem);

    const int tid  = threadIdx.x;
    const int wid  = tid >> 5;
    const int lane = tid & 31;
    const int wm   = (wid >> 2) * 64;
    const int wn   = (wid & 3) * 32;
    const int np   = *np_ptr;

    const int arow  = wm + (lane & 15);
    const int acolb = (lane >> 4) * 8;
    const int brow  = wn + (lane & 7) + ((lane >> 4) << 3);
    const int bcolb = ((lane >> 3) & 1) << 3;
    const int a7 = arow & 7;
    const int b7 = brow & 7;
    const int mq = lane >> 2;
    const int nq = (lane & 3) * 2;

    for (int t = blockIdx.x; t < ntiles; t += gridDim.x) {
        int by, bx;
        if (MODE == 1) {
            by = (int)((sqrtf(8.f * (float)t + 1.f) - 1.f) * 0.5f);
            while ((by + 1) * (by + 2) / 2 <= t) by++;
            while (by * (by + 1) / 2 > t) by--;
            bx = t - by * (by + 1) / 2;
        } else if (MODE == 2) {
            by = (ntiles / nbx) - 1 - (t / nbx);    // heavy rows first
            bx = t % nbx;
        } else {
            by = t / nbx;
            bx = t % nbx;
        }
        const int m0 = by * 128;
        const int n0 = bx * 128;

        if (MODE == 0) { if (m0 + 128 <= np) continue; }
        if (MODE == 1) {
            if (m0 + 128 <= np) continue;
            if (n0 + 128 <= np) continue;
        }

        int c0 = 0, c1 = K >> 6;
        if (MODE == 2) { c0 = np >> 6; c1 = (m0 + 128) >> 6; }
        const int nchunks = c1 - c0;

        float acc[4][4][4];
        #pragma unroll
        for (int i = 0; i < 4; i++)
            #pragma unroll
            for (int j = 0; j < 4; j++)
                #pragma unroll
                for (int e = 0; e < 4; e++) acc[i][j][e] = 0.f;

        auto prefetch = [&](int c, int stage) {
            const int kc = c << 6;
            const uint32_t st = sbase + stage * STAGE_B;
            #pragma unroll
            for (int u = 0; u < 4; u++) {
                const int idx = tid + u * 256;
                const int r   = idx >> 3;
                const int seg = idx & 7;
                const uint32_t d = (uint32_t)(r * 128 + ((seg ^ (r & 7)) << 4));
                CP_ASYNC16(st + 0 * TILE_B + d, &Ah[(size_t)(m0 + r) * lda + kc + seg * 8]);
                CP_ASYNC16(st + 1 * TILE_B + d, &Bh[(size_t)(n0 + r) * ldb + kc + seg * 8]);
            }
        };

        if (nchunks > 0) {
            prefetch(c0, 0); CP_COMMIT();
            if (nchunks > 1) prefetch(c0 + 1, 1);
            CP_COMMIT();
            int s_cur = 0, s_pf = 2;
            for (int i = 0; i < nchunks; i++) {
                CP_WAIT1();
                __syncthreads();
                if (i + 2 < nchunks) prefetch(c0 + i + 2, s_pf);
                CP_COMMIT();
                const uint32_t aHb = sbase + s_cur * STAGE_B;
                const uint32_t bHb = aHb + TILE_B;
                #pragma unroll
                for (int ks = 0; ks < 4; ks++) {
                    const int k0 = ks * 16;
                    const uint32_t aswz = (uint32_t)(((((k0 + acolb) >> 3) ^ a7) << 4));
                    const uint32_t bswz = (uint32_t)(((((k0 + bcolb) >> 3) ^ b7) << 4));
                    const uint32_t aAddr0 = aHb + (uint32_t)(arow * 128) + aswz;
                    uint32_t aH[4][4];
                    uint32_t bp[2][4];
                    ldsm_x4(aH[0], aAddr0);
                    ldsm_x4(bp[0], bHb + (uint32_t)(brow * 128) + bswz);
                    ldsm_x4(aH[1], aAddr0 + (uint32_t)(16 * 128));
                    ldsm_x4(bp[1], bHb + (uint32_t)((brow + 16) * 128) + bswz);
                    ldsm_x4(aH[2], aAddr0 + (uint32_t)(32 * 128));
                    ldsm_x4(aH[3], aAddr0 + (uint32_t)(48 * 128));
                    #pragma unroll
                    for (int mt = 0; mt < 4; mt++) {
                        mma16816(acc[mt][0], aH[mt], &bp[0][0]);
                        mma16816(acc[mt][1], aH[mt], &bp[0][2]);
                        mma16816(acc[mt][2], aH[mt], &bp[1][0]);
                        mma16816(acc[mt][3], aH[mt], &bp[1][2]);
                    }
                }
                s_cur = (s_cur == 2) ? 0 : s_cur + 1;
                s_pf  = (s_pf  == 2) ? 0 : s_pf  + 1;
            }
        }

        // -------- epilogue ----------------------------------------------------
        if (MODE == 0) {
            const int region = n0 / F;      // 0=q 1=k 2=v
            if (region < 2) {
                __half* D = region ? kh : qh;
                const int nb = n0 - region * F;
                #pragma unroll
                for (int mt = 0; mt < 4; mt++) {
                    const int r0 = m0 + wm + mt * 16 + mq;
                    #pragma unroll
                    for (int nt = 0; nt < 4; nt++) {
                        const int nl = nb + wn + nt * 8 + nq;
                        const int gn = n0 + wn + nt * 8 + nq;
                        __half h0 = __float2half(acc[mt][nt][0] + bias[gn]);
                        __half h1 = __float2half(acc[mt][nt][1] + bias[gn + 1]);
                        *(__half2*)&D[(size_t)r0 * F + nl] = __half2(h0, h1);
                        h0 = __float2half(acc[mt][nt][2] + bias[gn]);
                        h1 = __float2half(acc[mt][nt][3] + bias[gn + 1]);
                        *(__half2*)&D[(size_t)(r0 + 8) * F + nl] = __half2(h0, h1);
                    }
                }
            } else {
                CP_WAIT0();
                __half* smem_t = (__half*)smem;
                const int vb = n0 - 2 * F;
                __syncthreads();
                #pragma unroll
                for (int mt = 0; mt < 4; mt++) {
                    const int ml = wm + mt * 16 + mq;
                    #pragma unroll
                    for (int nt = 0; nt < 4; nt++) {
                        const int nl = wn + nt * 8 + nq;
                        const int gn = n0 + wn + nt * 8 + nq;
                        #pragma unroll
                        for (int e = 0; e < 4; e++) {
                            const int nn = nl + (e & 1);
                            const int mm = ml + (e >> 1) * 8;
                            smem_t[nn * PT + mm] = __float2half(acc[mt][nt][e] + bias[gn + (e & 1)]);
                        }
                    }
                }
                __syncthreads();
                const int r = tid >> 1;
                const int sg = (tid & 1) * 64;
                const uint4* src = (const uint4*)&smem_t[r * PT + sg];
                uint4* dst = (uint4*)&vTh[(size_t)(vb + r) * S + m0 + sg];
                #pragma unroll
                for (int j = 0; j < 8; j++) dst[j] = src[j];
            }
        } else if (MODE == 1) {
            // att = exp(scale*s) masked; deterministic slotted rowsum -> psum
            CP_WAIT0();
            float (*rs)[4] = (float(*)[4])smem;      // [128][4]
            __syncthreads();
            __half* att = qh;               // att base passed via qh
            const int wcol = wid & 3;
            #pragma unroll
            for (int mt = 0; mt < 4; mt++) {
                const int r0l = wm + mt * 16 + mq;
                const int r1l = r0l + 8;
                const int gi0 = m0 + r0l;
                const int gi1 = m0 + r1l;
                float s0 = 0.f, s1 = 0.f;
                #pragma unroll
                for (int nt = 0; nt < 4; nt++) {
                    const int gj = n0 + wn + nt * 8 + nq;
                    float p00 = (gi0 >= np && gj     >= np && gj     <= gi0) ? __expf(acc[mt][nt][0] * scale) : 0.f;
                    float p01 = (gi0 >= np && gj + 1 >= np && gj + 1 <= gi0) ? __expf(acc[mt][nt][1] * scale) : 0.f;
                    float p10 = (gi1 >= np && gj     >= np && gj     <= gi1) ? __expf(acc[mt][nt][2] * scale) : 0.f;
                    float p11 = (gi1 >= np && gj + 1 >= np && gj + 1 <= gi1) ? __expf(acc[mt][nt][3] * scale) : 0.f;
                    *(__half2*)&att[(size_t)gi0 * S + gj] = __half2(__float2half(p00), __float2half(p01));
                    *(__half2*)&att[(size_t)gi1 * S + gj] = __half2(__float2half(p10), __float2half(p11));
                    s0 += p00 + p01;
                    s1 += p10 + p11;
                }
                s0 += __shfl_xor_sync(0xffffffffu, s0, 1);
                s0 += __shfl_xor_sync(0xffffffffu, s0, 2);
                s1 += __shfl_xor_sync(0xffffffffu, s1, 1);
                s1 += __shfl_xor_sync(0xffffffffu, s1, 2);
                if ((lane & 3) == 0) {
                    rs[r0l][wcol] = s0;
                    rs[r1l][wcol] = s1;
                }
            }
            __syncthreads();
            if (tid < 128) {
                float v = ((rs[tid][0] + rs[tid][1]) + (rs[tid][2] + rs[tid][3]));
                outf[(size_t)(m0 + tid) * 32 + (n0 >> 7)] = v;
            }
        } else {
            // out = acc * inv[row]  (bias = g_inv)
            #pragma unroll
            for (int mt = 0; mt < 4; mt++) {
                const int r0 = m0 + wm + mt * 16 + mq;
                const float i0 = bias[r0];
                const float i1 = bias[r0 + 8];
                #pragma unroll
                for (int nt = 0; nt < 4; nt++) {
                    const int gn = n0 + wn + nt * 8 + nq;
                    float2 p0, p1;
                    p0.x = acc[mt][nt][0] * i0;  p0.y = acc[mt][nt][1] * i0;
                    p1.x = acc[mt][nt][2] * i1;  p1.y = acc[mt][nt][3] * i1;
                    *(float2*)&outf[(size_t)r0 * ldo + gn]       = p0;
                    *(float2*)&outf[(size_t)(r0 + 8) * ldo + gn] = p1;
                }
            }
        }
        __syncthreads();   // smem ring safe before next tile's prefetch
    }
}

// ---------------- rowinv: inv[i] = 1/sum(psum[i][np>>7 .. i>>7]) -------------
__global__ __launch_bounds__(256) void rowinv_kernel(
    const float* __restrict__ psum, float* __restrict__ inv,
    int S, const int* __restrict__ np_ptr)
{
    const int i = blockIdx.x * 8 + (threadIdx.x >> 5);
    const int lane = threadIdx.x & 31;
    if (i >= S) return;
    const int np = *np_ptr;
    const int lo = np >> 7;
    const int hi = i >> 7;
    float v = 0.f;
    if (i >= np && lane >= lo && lane <= hi) v = psum[(size_t)i * 32 + lane];
    #pragma unroll
    for (int off = 16; off > 0; off >>= 1) v += __shfl_xor_sync(0xffffffffu, v, off);
    if (lane == 0) inv[i] = (i >= np && v > 0.f) ? 1.f / v : 0.f;
}

// ---------------- fp32 -> fp16 (hi only) ------------------------------------
__global__ __launch_bounds__(256) void convert_h_kernel(
    const float* __restrict__ in, __half* __restrict__ h, size_t n4)
{
    for (size_t i = blockIdx.x * 256 + threadIdx.x; i < n4; i += (size_t)gridDim.x * 256) {
        float4 v = ((const float4*)in)[i];
        ((__half2*)h)[i * 2 + 0] = __half2(__float2half(v.x), __float2half(v.y));
        ((__half2*)h)[i * 2 + 1] = __half2(__float2half(v.z), __float2half(v.w));
    }
}

// ---------------- wide transpose (fp32 -> fp16): Th[c][r] = W[r][c] ---------
__global__ __launch_bounds__(256) void transpose_h_kernel(
    const float* __restrict__ W, __half* __restrict__ Th, int rows, int cols)
{
    __shared__ __half sm[64][72];
    const int bx = blockIdx.x * 64;
    const int by = blockIdx.y * 64;
    const int t  = threadIdx.x;
    const int r  = t >> 2;
    const int tg = t & 3;
    const float* src = &W[(size_t)(by + r) * cols + bx];
    #pragma unroll
    for (int j = 0; j < 4; j++) {
        const int cl = j * 16 + tg * 4;
        float4 v = *(const float4*)&src[cl];
        sm[cl + 0][r] = __float2half(v.x);
        sm[cl + 1][r] = __float2half(v.y);
        sm[cl + 2][r] = __float2half(v.z);
        sm[cl + 3][r] = __float2half(v.w);
    }
    __syncthreads();
    const int orl  = t >> 2;
    const int part = (t & 3) * 16;
    __half* dst = &Th[(size_t)(bx + orl) * rows + by + part];
    *(uint4*)&dst[0] = *(const uint4*)&sm[orl][part];
    *(uint4*)&dst[8] = *(const uint4*)&sm[orl][part + 8];
}

// ============================================================================
extern "C" void kernel_launch(void* const* d_in, const int* in_sizes, int n_in,
                              void* d_out, int out_size)
{
    const float* x  = (const float*)d_in[0];
    const float* W  = (const float*)d_in[1];
    const float* b  = (const float*)d_in[2];
    const int*   np = (const int*)  d_in[3];

    const int F3 = in_sizes[2];      // 6144
    const int F  = F3 / 3;           // 2048
    const int S  = in_sizes[0] / F;  // 4096
    float* out = (float*)d_out;

    __half *xh, *Wth, *qh, *kh, *vTh, *atth;
    float *psum, *inv;
    cudaGetSymbolAddress((void**)&xh,  g_xh);
    cudaGetSymbolAddress((void**)&Wth, g_Wth);
    cudaGetSymbolAddress((void**)&qh,  g_qh);
    cudaGetSymbolAddress((void**)&kh,  g_kh);
    cudaGetSymbolAddress((void**)&vTh, g_vTh);
    cudaGetSymbolAddress((void**)&atth, g_atth);
    cudaGetSymbolAddress((void**)&psum, g_psum);
    cudaGetSymbolAddress((void**)&inv,  g_inv);

    cudaFuncSetAttribute(hmma_gemm<0>, cudaFuncAttributeMaxDynamicSharedMemorySize, SMEM_BYTES);
    cudaFuncSetAttribute(hmma_gemm<1>, cudaFuncAttributeMaxDynamicSharedMemorySize, SMEM_BYTES);
    cudaFuncSetAttribute(hmma_gemm<2>, cudaFuncAttributeMaxDynamicSharedMemorySize, SMEM_BYTES);

    int nsm = 148;
    cudaDeviceGetAttribute(&nsm, cudaDevAttrMultiProcessorCount, 0);
    const int nslots = 2 * nsm;

    const float scale = 1.0f / sqrtf((float)F);

    convert_h_kernel<<<2048, 256>>>(x, xh, (size_t)S * F / 4);
    transpose_h_kernel<<<dim3(F3 / 64, F / 64), 256>>>(W, Wth, F, F3);

    // qkv = xh @ Wth^T + b -> q/k hi, vT hi  (persistent, row-major tiles)
    {
        const int nbx = F3 / 128, ntiles = nbx * (S / 128);
        hmma_gemm<0><<<(ntiles < nslots ? ntiles : nslots), 256, SMEM_BYTES>>>(
            xh, F, Wth, F, F, b, 1.0f, nullptr, 0,
            qh, kh, vTh, F, S, np, ntiles, nbx);
    }
    // scores -> att = exp(scale * q@k^T) masked, + psum  (persistent, triangular)
    {
        const int nb = S / 128, ntiles = nb * (nb + 1) / 2;
        hmma_gemm<1><<<(ntiles < nslots ? ntiles : nslots), 256, SMEM_BYTES>>>(
            qh, F, kh, F, F, nullptr, scale, psum, 0,
            atth, nullptr, nullptr, F, S, np, ntiles, nb);
    }
    // inv[i] = 1 / rowsum
    rowinv_kernel<<<S / 8, 256>>>(psum, inv, S, np);

    // out = (att @ v) * inv[row]  (persistent, LPT heavy-first)
    {
        const int nbx = F / 128, ntiles = nbx * (S / 128);
        hmma_gemm<2><<<(ntiles < nslots ? ntiles : nslots), 256, SMEM_BYTES>>>(
            atth, S, vTh, S, S, inv, 1.0f, out, F,
            nullptr, nullptr, nullptr, F, S, np, ntiles, nbx);
    }
}

// round 16
// speedup vs baseline: 1.1261x; 1.1261x over previous
#include <cuda_runtime.h>
#include <cuda_fp16.h>
#include <math.h>
#include <stdint.h>

// ============================================================================
// PaddedSHCSA, single-pass fp16 GEMMs, fused softmax (rel_err ~6e-4).
// Round 16: R14 base (non-persistent; tri scores grid, LPT out, wide
// transpose, slotted rowsum) + rowinv FUSED into out-GEMM prologue
// (one fewer kernel; inv computed per-CTA from psum, deterministic).
// ============================================================================

#define S_DIM   4096
#define F_DIM   2048
#define F3_DIM  6144

__device__ __half g_xh [(size_t)S_DIM * F_DIM];
__device__ __half g_Wth[(size_t)F3_DIM * F_DIM];   // W^T hi [3F][F]
__device__ __half g_qh [(size_t)S_DIM * F_DIM];
__device__ __half g_kh [(size_t)S_DIM * F_DIM];
__device__ __half g_vTh[(size_t)F_DIM * S_DIM];    // v^T [F][S]
__device__ __half g_atth[(size_t)S_DIM * S_DIM];   // unnormalized exp
__device__ float  g_psum[(size_t)S_DIM * 32];      // per (row, n-block) sums

// ---------------- low-level helpers -----------------------------------------
__device__ __forceinline__ uint32_t smem_u32(const void* p) {
    uint32_t a;
    asm("{ .reg .u64 t; cvta.to.shared.u64 t, %1; cvt.u32.u64 %0, t; }" : "=r"(a) : "l"(p));
    return a;
}
#define CP_ASYNC16(dst_u32, src_ptr) \
    asm volatile("cp.async.cg.shared.global [%0], [%1], 16;" :: "r"(dst_u32), "l"(src_ptr))
#define CP_COMMIT()  asm volatile("cp.async.commit_group;" ::: "memory")
#define CP_WAIT1()   asm volatile("cp.async.wait_group 1;" ::: "memory")
#define CP_WAIT0()   asm volatile("cp.async.wait_group 0;" ::: "memory")

__device__ __forceinline__ void ldsm_x4(uint32_t* r, uint32_t addr) {
    asm volatile("ldmatrix.sync.aligned.m8n8.x4.shared.b16 {%0,%1,%2,%3}, [%4];"
        : "=r"(r[0]), "=r"(r[1]), "=r"(r[2]), "=r"(r[3]) : "r"(addr));
}
__device__ __forceinline__ void mma16816(float* c, const uint32_t* a, const uint32_t* b) {
    asm volatile("mma.sync.aligned.m16n8k16.row.col.f32.f16.f16.f32 "
        "{%0,%1,%2,%3}, {%4,%5,%6,%7}, {%8,%9}, {%0,%1,%2,%3};"
        : "+f"(c[0]), "+f"(c[1]), "+f"(c[2]), "+f"(c[3])
        : "r"(a[0]), "r"(a[1]), "r"(a[2]), "r"(a[3]), "r"(b[0]), "r"(b[1]));
}

// ---------------- smem layout -----------------------------------------------
static constexpr int TILE_B = 128 * 128;             // 16384 B
static constexpr int STAGE_B = 2 * TILE_B;           // Ah Bh = 32768 B
static constexpr int NSTAGE = 3;
static constexpr int RING_B = NSTAGE * STAGE_B;      // 98304 B
static constexpr int SMEM_BYTES = RING_B + 512;      // + inv[128] (2 CTAs/SM ok)
static constexpr int PT = 136;                       // vT transpose staging pitch

// ============================================================================
// 256 threads, 8 warps 2x4, warp tile 64x32, BK=64 swizzled, 3-stage ring.
// MODE 0: qkv (bias; -> q/k hi rows, vT hi transposed)  [2D grid]
// MODE 1: scores->att: exp(scale*s) masked -> att fp16 + psum  [1D tri grid]
// MODE 2: out: (att@v)*inv[row]; inv computed in prologue from psum (bias);
//         k in [np, m0+128); LPT reversed-y order
// ============================================================================
template<int MODE>
__global__ __launch_bounds__(256, 2) void hmma_gemm(
    const __half* __restrict__ Ah, int lda,
    const __half* __restrict__ Bh, int ldb,
    int K, const float* __restrict__ bias, float scale,
    float* __restrict__ outf, int ldo,
    __half* __restrict__ qh, __half* __restrict__ kh,
    __half* __restrict__ vTh,
    int F, int S, const int* __restrict__ np_ptr)
{
    int by, bx;
    if (MODE == 1) {
        const int t = blockIdx.x;
        by = (int)((sqrtf(8.f * (float)t + 1.f) - 1.f) * 0.5f);
        while ((by + 1) * (by + 2) / 2 <= t) by++;
        while (by * (by + 1) / 2 > t) by--;
        bx = t - by * (by + 1) / 2;
    } else {
        by = (MODE == 2) ? (gridDim.y - 1 - blockIdx.y) : blockIdx.y;
        bx = blockIdx.x;
    }
    const int m0 = by * 128;
    const int n0 = bx * 128;
    const int np = *np_ptr;

    if (MODE == 0) { if (m0 + 128 <= np) return; }
    if (MODE == 1) {
        if (m0 + 128 <= np) return;
        if (n0 + 128 <= np) return;
    }

    int c0 = 0, c1 = K >> 6;                 // BK = 64
    if (MODE == 2) { c0 = np >> 6; c1 = (m0 + 128) >> 6; }
    const int nchunks = c1 - c0;

    extern __shared__ __align__(128) char smem[];
    const uint32_t sbase = smem_u32(smem);
    float* sm_inv = (float*)(smem + RING_B);

    const int tid  = threadIdx.x;
    const int wid  = tid >> 5;
    const int lane = tid & 31;
    const int wm   = (wid >> 2) * 64;
    const int wn   = (wid & 3) * 32;

    float acc[4][4][4];
    #pragma unroll
    for (int i = 0; i < 4; i++)
        #pragma unroll
        for (int j = 0; j < 4; j++)
            #pragma unroll
            for (int e = 0; e < 4; e++) acc[i][j][e] = 0.f;

    auto prefetch = [&](int c, int stage) {
        const int kc = c << 6;
        const uint32_t st = sbase + stage * STAGE_B;
        #pragma unroll
        for (int t = 0; t < 4; t++) {
            const int idx = tid + t * 256;
            const int r   = idx >> 3;
            const int seg = idx & 7;
            const uint32_t d = (uint32_t)(r * 128 + ((seg ^ (r & 7)) << 4));
            CP_ASYNC16(st + 0 * TILE_B + d, &Ah[(size_t)(m0 + r) * lda + kc + seg * 8]);
            CP_ASYNC16(st + 1 * TILE_B + d, &Bh[(size_t)(n0 + r) * ldb + kc + seg * 8]);
        }
    };

    const int arow  = wm + (lane & 15);
    const int acolb = (lane >> 4) * 8;
    const int brow  = wn + (lane & 7) + ((lane >> 4) << 3);
    const int bcolb = ((lane >> 3) & 1) << 3;
    const int a7 = arow & 7;
    const int b7 = brow & 7;

    if (nchunks > 0) {
        prefetch(c0, 0); CP_COMMIT();
        if (nchunks > 1) prefetch(c0 + 1, 1);
        CP_COMMIT();

        // MODE 2 prologue: inv for this CTA's 128 rows (overlaps prefetch)
        if (MODE == 2) {
            if (tid < 128) {
                const int row = m0 + tid;
                const int lo = np >> 7;
                const int hi = row >> 7;
                const float* pr = &bias[(size_t)row * 32];   // bias = psum base
                float v = 0.f;
                for (int j = lo; j <= hi; j++) v += pr[j];
                sm_inv[tid] = (row >= np && v > 0.f) ? 1.f / v : 0.f;
            }
            __syncthreads();
        }

        int s_cur = 0, s_pf = 2;
        for (int i = 0; i < nchunks; i++) {
            CP_WAIT1();
            __syncthreads();
            if (i + 2 < nchunks) prefetch(c0 + i + 2, s_pf);
            CP_COMMIT();
            const uint32_t aHb = sbase + s_cur * STAGE_B;
            const uint32_t bHb = aHb + TILE_B;
            #pragma unroll
            for (int ks = 0; ks < 4; ks++) {
                const int k0 = ks * 16;
                const uint32_t aswz = (uint32_t)(((((k0 + acolb) >> 3) ^ a7) << 4));
                const uint32_t bswz = (uint32_t)(((((k0 + bcolb) >> 3) ^ b7) << 4));
                const uint32_t aAddr0 = aHb + (uint32_t)(arow * 128) + aswz;
                uint32_t aH[4][4];
                uint32_t bp[2][4];
                ldsm_x4(aH[0], aAddr0);
                ldsm_x4(bp[0], bHb + (uint32_t)(brow * 128) + bswz);
                ldsm_x4(aH[1], aAddr0 + (uint32_t)(16 * 128));
                ldsm_x4(bp[1], bHb + (uint32_t)((brow + 16) * 128) + bswz);
                ldsm_x4(aH[2], aAddr0 + (uint32_t)(32 * 128));
                ldsm_x4(aH[3], aAddr0 + (uint32_t)(48 * 128));
                #pragma unroll
                for (int mt = 0; mt < 4; mt++) {
                    mma16816(acc[mt][0], aH[mt], &bp[0][0]);
                    mma16816(acc[mt][1], aH[mt], &bp[0][2]);
                    mma16816(acc[mt][2], aH[mt], &bp[1][0]);
                    mma16816(acc[mt][3], aH[mt], &bp[1][2]);
                }
            }
            s_cur = (s_cur == 2) ? 0 : s_cur + 1;
            s_pf  = (s_pf  == 2) ? 0 : s_pf  + 1;
        }
    }

    // ---------------- epilogue ----------------------------------------------
    const int mq = lane >> 2;
    const int nq = (lane & 3) * 2;

    if (MODE == 0) {
        const int region = n0 / F;      // 0=q 1=k 2=v
        if (region < 2) {
            __half* D = region ? kh : qh;
            const int nb = n0 - region * F;
            #pragma unroll
            for (int mt = 0; mt < 4; mt++) {
                const int r0 = m0 + wm + mt * 16 + mq;
                #pragma unroll
                for (int nt = 0; nt < 4; nt++) {
                    const int nl = nb + wn + nt * 8 + nq;
                    const int gn = n0 + wn + nt * 8 + nq;
                    __half h0 = __float2half(acc[mt][nt][0] + bias[gn]);
                    __half h1 = __float2half(acc[mt][nt][1] + bias[gn + 1]);
                    *(__half2*)&D[(size_t)r0 * F + nl] = __half2(h0, h1);
                    h0 = __float2half(acc[mt][nt][2] + bias[gn]);
                    h1 = __float2half(acc[mt][nt][3] + bias[gn + 1]);
                    *(__half2*)&D[(size_t)(r0 + 8) * F + nl] = __half2(h0, h1);
                }
            }
        } else {
            CP_WAIT0();
            __half* smem_t = (__half*)smem;
            const int vb = n0 - 2 * F;
            __syncthreads();
            #pragma unroll
            for (int mt = 0; mt < 4; mt++) {
                const int ml = wm + mt * 16 + mq;
                #pragma unroll
                for (int nt = 0; nt < 4; nt++) {
                    const int nl = wn + nt * 8 + nq;
                    const int gn = n0 + wn + nt * 8 + nq;
                    #pragma unroll
                    for (int e = 0; e < 4; e++) {
                        const int nn = nl + (e & 1);
                        const int mm = ml + (e >> 1) * 8;
                        smem_t[nn * PT + mm] = __float2half(acc[mt][nt][e] + bias[gn + (e & 1)]);
                    }
                }
            }
            __syncthreads();
            const int r = tid >> 1;
            const int sg = (tid & 1) * 64;
            const uint4* src = (const uint4*)&smem_t[r * PT + sg];
            uint4* dst = (uint4*)&vTh[(size_t)(vb + r) * S + m0 + sg];
            #pragma unroll
            for (int j = 0; j < 8; j++) dst[j] = src[j];
        }
    } else if (MODE == 1) {
        // att = exp(scale*s) masked; deterministic slotted rowsum -> psum
        CP_WAIT0();
        float (*rs)[4] = (float(*)[4])smem;      // [128][4]
        __syncthreads();
        __half* att = qh;               // att base passed via qh
        const int wcol = wid & 3;
        #pragma unroll
        for (int mt = 0; mt < 4; mt++) {
            const int r0l = wm + mt * 16 + mq;
            const int r1l = r0l + 8;
            const int gi0 = m0 + r0l;
            const int gi1 = m0 + r1l;
            float s0 = 0.f, s1 = 0.f;
            #pragma unroll
            for (int nt = 0; nt < 4; nt++) {
                const int gj = n0 + wn + nt * 8 + nq;
                float p00 = (gi0 >= np && gj     >= np && gj     <= gi0) ? __expf(acc[mt][nt][0] * scale) : 0.f;
                float p01 = (gi0 >= np && gj + 1 >= np && gj + 1 <= gi0) ? __expf(acc[mt][nt][1] * scale) : 0.f;
                float p10 = (gi1 >= np && gj     >= np && gj     <= gi1) ? __expf(acc[mt][nt][2] * scale) : 0.f;
                float p11 = (gi1 >= np && gj + 1 >= np && gj + 1 <= gi1) ? __expf(acc[mt][nt][3] * scale) : 0.f;
                *(__half2*)&att[(size_t)gi0 * S + gj] = __half2(__float2half(p00), __float2half(p01));
                *(__half2*)&att[(size_t)gi1 * S + gj] = __half2(__float2half(p10), __float2half(p11));
                s0 += p00 + p01;
                s1 += p10 + p11;
            }
            s0 += __shfl_xor_sync(0xffffffffu, s0, 1);
            s0 += __shfl_xor_sync(0xffffffffu, s0, 2);
            s1 += __shfl_xor_sync(0xffffffffu, s1, 1);
            s1 += __shfl_xor_sync(0xffffffffu, s1, 2);
            if ((lane & 3) == 0) {
                rs[r0l][wcol] = s0;
                rs[r1l][wcol] = s1;
            }
        }
        __syncthreads();
        if (tid < 128) {
            float v = ((rs[tid][0] + rs[tid][1]) + (rs[tid][2] + rs[tid][3]));
            outf[(size_t)(m0 + tid) * 32 + (n0 >> 7)] = v;
        }
    } else {
        // out = acc * inv[row]  (inv in smem, computed in prologue)
        #pragma unroll
        for (int mt = 0; mt < 4; mt++) {
            const int rl = wm + mt * 16 + mq;
            const int r0 = m0 + rl;
            const float i0 = sm_inv[rl];
            const float i1 = sm_inv[rl + 8];
            #pragma unroll
            for (int nt = 0; nt < 4; nt++) {
                const int gn = n0 + wn + nt * 8 + nq;
                float2 p0, p1;
                p0.x = acc[mt][nt][0] * i0;  p0.y = acc[mt][nt][1] * i0;
                p1.x = acc[mt][nt][2] * i1;  p1.y = acc[mt][nt][3] * i1;
                *(float2*)&outf[(size_t)r0 * ldo + gn]       = p0;
                *(float2*)&outf[(size_t)(r0 + 8) * ldo + gn] = p1;
            }
        }
    }
}

// ---------------- fp32 -> fp16 (hi only) ------------------------------------
__global__ __launch_bounds__(256) void convert_h_kernel(
    const float* __restrict__ in, __half* __restrict__ h, size_t n4)
{
    for (size_t i = blockIdx.x * 256 + threadIdx.x; i < n4; i += (size_t)gridDim.x * 256) {
        float4 v = ((const float4*)in)[i];
        ((__half2*)h)[i * 2 + 0] = __half2(__float2half(v.x), __float2half(v.y));
        ((__half2*)h)[i * 2 + 1] = __half2(__float2half(v.z), __float2half(v.w));
    }
}

// ---------------- wide transpose (fp32 -> fp16): Th[c][r] = W[r][c] ---------
__global__ __launch_bounds__(256) void transpose_h_kernel(
    const float* __restrict__ W, __half* __restrict__ Th, int rows, int cols)
{
    __shared__ __half sm[64][72];
    const int bx = blockIdx.x * 64;
    const int by = blockIdx.y * 64;
    const int t  = threadIdx.x;
    const int r  = t >> 2;
    const int tg = t & 3;
    const float* src = &W[(size_t)(by + r) * cols + bx];
    #pragma unroll
    for (int j = 0; j < 4; j++) {
        const int cl = j * 16 + tg * 4;
        float4 v = *(const float4*)&src[cl];
        sm[cl + 0][r] = __float2half(v.x);
        sm[cl + 1][r] = __float2half(v.y);
        sm[cl + 2][r] = __float2half(v.z);
        sm[cl + 3][r] = __float2half(v.w);
    }
    __syncthreads();
    const int orl  = t >> 2;
    const int part = (t & 3) * 16;
    __half* dst = &Th[(size_t)(bx + orl) * rows + by + part];
    *(uint4*)&dst[0] = *(const uint4*)&sm[orl][part];
    *(uint4*)&dst[8] = *(const uint4*)&sm[orl][part + 8];
}

// ============================================================================
extern "C" void kernel_launch(void* const* d_in, const int* in_sizes, int n_in,
                              void* d_out, int out_size)
{
    const float* x  = (const float*)d_in[0];
    const float* W  = (const float*)d_in[1];
    const float* b  = (const float*)d_in[2];
    const int*   np = (const int*)  d_in[3];

    const int F3 = in_sizes[2];      // 6144
    const int F  = F3 / 3;           // 2048
    const int S  = in_sizes[0] / F;  // 4096
    float* out = (float*)d_out;

    __half *xh, *Wth, *qh, *kh, *vTh, *atth;
    float *psum;
    cudaGetSymbolAddress((void**)&xh,  g_xh);
    cudaGetSymbolAddress((void**)&Wth, g_Wth);
    cudaGetSymbolAddress((void**)&qh,  g_qh);
    cudaGetSymbolAddress((void**)&kh,  g_kh);
    cudaGetSymbolAddress((void**)&vTh, g_vTh);
    cudaGetSymbolAddress((void**)&atth, g_atth);
    cudaGetSymbolAddress((void**)&psum, g_psum);

    cudaFuncSetAttribute(hmma_gemm<0>, cudaFuncAttributeMaxDynamicSharedMemorySize, SMEM_BYTES);
    cudaFuncSetAttribute(hmma_gemm<1>, cudaFuncAttributeMaxDynamicSharedMemorySize, SMEM_BYTES);
    cudaFuncSetAttribute(hmma_gemm<2>, cudaFuncAttributeMaxDynamicSharedMemorySize, SMEM_BYTES);

    const float scale = 1.0f / sqrtf((float)F);

    convert_h_kernel<<<2048, 256>>>(x, xh, (size_t)S * F / 4);
    transpose_h_kernel<<<dim3(F3 / 64, F / 64), 256>>>(W, Wth, F, F3);

    // qkv = xh @ Wth^T + b -> q/k hi, vT hi
    hmma_gemm<0><<<dim3(F3 / 128, S / 128), 256, SMEM_BYTES>>>(
        xh, F, Wth, F, F, b, 1.0f, nullptr, 0,
        qh, kh, vTh, F, S, np);

    // scores -> att = exp(scale * q@k^T) masked, + psum (triangular 1D grid)
    const int nb = S / 128;
    hmma_gemm<1><<<nb * (nb + 1) / 2, 256, SMEM_BYTES>>>(
        qh, F, kh, F, F, nullptr, scale, psum, 0,
        atth, nullptr, nullptr, F, S, np);

    // out = (att @ v) * inv[row]  (inv fused into prologue; LPT reversed-y)
    hmma_gemm<2><<<dim3(F / 128, S / 128), 256, SMEM_BYTES>>>(
        atth, S, vTh, S, S, psum, 1.0f, out, F,
        nullptr, nullptr, nullptr, F, S, np);
}

// round 17
// speedup vs baseline: 1.1337x; 1.0067x over previous
#include <cuda_runtime.h>
#include <cuda_fp16.h>
#include <math.h>
#include <stdint.h>

// ============================================================================
// PaddedSHCSA, single-pass fp16 GEMMs, fused softmax (rel_err ~6e-4).
// Round 17: R14 base (tri scores grid, LPT out, wide transpose, slotted
// rowsum, separate rowinv) + coalesced att stores (smem-staged, 128B rows).
// ============================================================================

#define S_DIM   4096
#define F_DIM   2048
#define F3_DIM  6144

__device__ __half g_xh [(size_t)S_DIM * F_DIM];
__device__ __half g_Wth[(size_t)F3_DIM * F_DIM];   // W^T hi [3F][F]
__device__ __half g_qh [(size_t)S_DIM * F_DIM];
__device__ __half g_kh [(size_t)S_DIM * F_DIM];
__device__ __half g_vTh[(size_t)F_DIM * S_DIM];    // v^T [F][S]
__device__ __half g_atth[(size_t)S_DIM * S_DIM];   // unnormalized exp
__device__ float  g_psum[(size_t)S_DIM * 32];      // per (row, n-block) sums
__device__ float  g_inv [S_DIM];                   // 1/rowsum (0 if padded)

// ---------------- low-level helpers -----------------------------------------
__device__ __forceinline__ uint32_t smem_u32(const void* p) {
    uint32_t a;
    asm("{ .reg .u64 t; cvta.to.shared.u64 t, %1; cvt.u32.u64 %0, t; }" : "=r"(a) : "l"(p));
    return a;
}
#define CP_ASYNC16(dst_u32, src_ptr) \
    asm volatile("cp.async.cg.shared.global [%0], [%1], 16;" :: "r"(dst_u32), "l"(src_ptr))
#define CP_COMMIT()  asm volatile("cp.async.commit_group;" ::: "memory")
#define CP_WAIT1()   asm volatile("cp.async.wait_group 1;" ::: "memory")
#define CP_WAIT0()   asm volatile("cp.async.wait_group 0;" ::: "memory")

__device__ __forceinline__ void ldsm_x4(uint32_t* r, uint32_t addr) {
    asm volatile("ldmatrix.sync.aligned.m8n8.x4.shared.b16 {%0,%1,%2,%3}, [%4];"
        : "=r"(r[0]), "=r"(r[1]), "=r"(r[2]), "=r"(r[3]) : "r"(addr));
}
__device__ __forceinline__ void mma16816(float* c, const uint32_t* a, const uint32_t* b) {
    asm volatile("mma.sync.aligned.m16n8k16.row.col.f32.f16.f16.f32 "
        "{%0,%1,%2,%3}, {%4,%5,%6,%7}, {%8,%9}, {%0,%1,%2,%3};"
        : "+f"(c[0]), "+f"(c[1]), "+f"(c[2]), "+f"(c[3])
        : "r"(a[0]), "r"(a[1]), "r"(a[2]), "r"(a[3]), "r"(b[0]), "r"(b[1]));
}

// ---------------- smem layout -----------------------------------------------
static constexpr int TILE_B = 128 * 128;             // 16384 B
static constexpr int STAGE_B = 2 * TILE_B;           // Ah Bh = 32768 B
static constexpr int NSTAGE = 3;
static constexpr int SMEM_BYTES = NSTAGE * STAGE_B;  // 98304 B (2 CTAs/SM)
static constexpr int PT = 136;                       // staging pitch (halves)

// ============================================================================
// 256 threads, 8 warps 2x4, warp tile 64x32, BK=64 swizzled, 3-stage ring.
// MODE 0: qkv (bias; -> q/k hi rows, vT hi transposed)  [2D grid]
// MODE 1: scores->att: exp(scale*s) masked -> att fp16 (smem-staged coalesced
//         stores) + psum  [1D triangular grid]
// MODE 2: out: (att@v)*inv[row] (bias=g_inv; k in [np, m0+128); LPT order)
// ============================================================================
template<int MODE>
__global__ __launch_bounds__(256, 2) void hmma_gemm(
    const __half* __restrict__ Ah, int lda,
    const __half* __restrict__ Bh, int ldb,
    int K, const float* __restrict__ bias, float scale,
    float* __restrict__ outf, int ldo,
    __half* __restrict__ qh, __half* __restrict__ kh,
    __half* __restrict__ vTh,
    int F, int S, const int* __restrict__ np_ptr)
{
    int by, bx;
    if (MODE == 1) {
        const int t = blockIdx.x;
        by = (int)((sqrtf(8.f * (float)t + 1.f) - 1.f) * 0.5f);
        while ((by + 1) * (by + 2) / 2 <= t) by++;
        while (by * (by + 1) / 2 > t) by--;
        bx = t - by * (by + 1) / 2;
    } else {
        by = (MODE == 2) ? (gridDim.y - 1 - blockIdx.y) : blockIdx.y;
        bx = blockIdx.x;
    }
    const int m0 = by * 128;
    const int n0 = bx * 128;
    const int np = *np_ptr;

    if (MODE == 0) { if (m0 + 128 <= np) return; }
    if (MODE == 1) {
        if (m0 + 128 <= np) return;
        if (n0 + 128 <= np) return;
    }

    int c0 = 0, c1 = K >> 6;                 // BK = 64
    if (MODE == 2) { c0 = np >> 6; c1 = (m0 + 128) >> 6; }
    const int nchunks = c1 - c0;

    extern __shared__ __align__(128) char smem[];
    const uint32_t sbase = smem_u32(smem);

    const int tid  = threadIdx.x;
    const int wid  = tid >> 5;
    const int lane = tid & 31;
    const int wm   = (wid >> 2) * 64;
    const int wn   = (wid & 3) * 32;

    float acc[4][4][4];
    #pragma unroll
    for (int i = 0; i < 4; i++)
        #pragma unroll
        for (int j = 0; j < 4; j++)
            #pragma unroll
            for (int e = 0; e < 4; e++) acc[i][j][e] = 0.f;

    auto prefetch = [&](int c, int stage) {
        const int kc = c << 6;
        const uint32_t st = sbase + stage * STAGE_B;
        #pragma unroll
        for (int t = 0; t < 4; t++) {
            const int idx = tid + t * 256;
            const int r   = idx >> 3;
            const int seg = idx & 7;
            const uint32_t d = (uint32_t)(r * 128 + ((seg ^ (r & 7)) << 4));
            CP_ASYNC16(st + 0 * TILE_B + d, &Ah[(size_t)(m0 + r) * lda + kc + seg * 8]);
            CP_ASYNC16(st + 1 * TILE_B + d, &Bh[(size_t)(n0 + r) * ldb + kc + seg * 8]);
        }
    };

    const int arow  = wm + (lane & 15);
    const int acolb = (lane >> 4) * 8;
    const int brow  = wn + (lane & 7) + ((lane >> 4) << 3);
    const int bcolb = ((lane >> 3) & 1) << 3;
    const int a7 = arow & 7;
    const int b7 = brow & 7;

    if (nchunks > 0) {
        prefetch(c0, 0); CP_COMMIT();
        if (nchunks > 1) prefetch(c0 + 1, 1);
        CP_COMMIT();
        int s_cur = 0, s_pf = 2;
        for (int i = 0; i < nchunks; i++) {
            CP_WAIT1();
            __syncthreads();
            if (i + 2 < nchunks) prefetch(c0 + i + 2, s_pf);
            CP_COMMIT();
            const uint32_t aHb = sbase + s_cur * STAGE_B;
            const uint32_t bHb = aHb + TILE_B;
            #pragma unroll
            for (int ks = 0; ks < 4; ks++) {
                const int k0 = ks * 16;
                const uint32_t aswz = (uint32_t)(((((k0 + acolb) >> 3) ^ a7) << 4));
                const uint32_t bswz = (uint32_t)(((((k0 + bcolb) >> 3) ^ b7) << 4));
                const uint32_t aAddr0 = aHb + (uint32_t)(arow * 128) + aswz;
                uint32_t aH[4][4];
                uint32_t bp[2][4];
                ldsm_x4(aH[0], aAddr0);
                ldsm_x4(bp[0], bHb + (uint32_t)(brow * 128) + bswz);
                ldsm_x4(aH[1], aAddr0 + (uint32_t)(16 * 128));
                ldsm_x4(bp[1], bHb + (uint32_t)((brow + 16) * 128) + bswz);
                ldsm_x4(aH[2], aAddr0 + (uint32_t)(32 * 128));
                ldsm_x4(aH[3], aAddr0 + (uint32_t)(48 * 128));
                #pragma unroll
                for (int mt = 0; mt < 4; mt++) {
                    mma16816(acc[mt][0], aH[mt], &bp[0][0]);
                    mma16816(acc[mt][1], aH[mt], &bp[0][2]);
                    mma16816(acc[mt][2], aH[mt], &bp[1][0]);
                    mma16816(acc[mt][3], aH[mt], &bp[1][2]);
                }
            }
            s_cur = (s_cur == 2) ? 0 : s_cur + 1;
            s_pf  = (s_pf  == 2) ? 0 : s_pf  + 1;
        }
    }

    // ---------------- epilogue ----------------------------------------------
    const int mq = lane >> 2;
    const int nq = (lane & 3) * 2;

    if (MODE == 0) {
        const int region = n0 / F;      // 0=q 1=k 2=v
        if (region < 2) {
            __half* D = region ? kh : qh;
            const int nb = n0 - region * F;
            #pragma unroll
            for (int mt = 0; mt < 4; mt++) {
                const int r0 = m0 + wm + mt * 16 + mq;
                #pragma unroll
                for (int nt = 0; nt < 4; nt++) {
                    const int nl = nb + wn + nt * 8 + nq;
                    const int gn = n0 + wn + nt * 8 + nq;
                    __half h0 = __float2half(acc[mt][nt][0] + bias[gn]);
                    __half h1 = __float2half(acc[mt][nt][1] + bias[gn + 1]);
                    *(__half2*)&D[(size_t)r0 * F + nl] = __half2(h0, h1);
                    h0 = __float2half(acc[mt][nt][2] + bias[gn]);
                    h1 = __float2half(acc[mt][nt][3] + bias[gn + 1]);
                    *(__half2*)&D[(size_t)(r0 + 8) * F + nl] = __half2(h0, h1);
                }
            }
        } else {
            CP_WAIT0();
            __half* smem_t = (__half*)smem;
            const int vb = n0 - 2 * F;
            __syncthreads();
            #pragma unroll
            for (int mt = 0; mt < 4; mt++) {
                const int ml = wm + mt * 16 + mq;
                #pragma unroll
                for (int nt = 0; nt < 4; nt++) {
                    const int nl = wn + nt * 8 + nq;
                    const int gn = n0 + wn + nt * 8 + nq;
                    #pragma unroll
                    for (int e = 0; e < 4; e++) {
                        const int nn = nl + (e & 1);
                        const int mm = ml + (e >> 1) * 8;
                        smem_t[nn * PT + mm] = __float2half(acc[mt][nt][e] + bias[gn + (e & 1)]);
                    }
                }
            }
            __syncthreads();
            const int r = tid >> 1;
            const int sg = (tid & 1) * 64;
            const uint4* src = (const uint4*)&smem_t[r * PT + sg];
            uint4* dst = (uint4*)&vTh[(size_t)(vb + r) * S + m0 + sg];
            #pragma unroll
            for (int j = 0; j < 8; j++) dst[j] = src[j];
        }
    } else if (MODE == 1) {
        // att = exp(scale*s) masked; staged in smem, coalesced 128B stores;
        // deterministic slotted rowsum -> psum
        CP_WAIT0();
        __half* smem_t = (__half*)smem;                       // [128][PT]
        float (*rs)[4] = (float(*)[4])(smem + 128 * PT * 2);  // rowsum slots
        __syncthreads();
        __half* att = qh;               // att base passed via qh
        const int wcol = wid & 3;
        #pragma unroll
        for (int mt = 0; mt < 4; mt++) {
            const int r0l = wm + mt * 16 + mq;
            const int r1l = r0l + 8;
            const int gi0 = m0 + r0l;
            const int gi1 = m0 + r1l;
            float s0 = 0.f, s1 = 0.f;
            #pragma unroll
            for (int nt = 0; nt < 4; nt++) {
                const int jl = wn + nt * 8 + nq;
                const int gj = n0 + jl;
                float p00 = (gi0 >= np && gj     >= np && gj     <= gi0) ? __expf(acc[mt][nt][0] * scale) : 0.f;
                float p01 = (gi0 >= np && gj + 1 >= np && gj + 1 <= gi0) ? __expf(acc[mt][nt][1] * scale) : 0.f;
                float p10 = (gi1 >= np && gj     >= np && gj     <= gi1) ? __expf(acc[mt][nt][2] * scale) : 0.f;
                float p11 = (gi1 >= np && gj + 1 >= np && gj + 1 <= gi1) ? __expf(acc[mt][nt][3] * scale) : 0.f;
                *(__half2*)&smem_t[r0l * PT + jl] = __half2(__float2half(p00), __float2half(p01));
                *(__half2*)&smem_t[r1l * PT + jl] = __half2(__float2half(p10), __float2half(p11));
                s0 += p00 + p01;
                s1 += p10 + p11;
            }
            s0 += __shfl_xor_sync(0xffffffffu, s0, 1);
            s0 += __shfl_xor_sync(0xffffffffu, s0, 2);
            s1 += __shfl_xor_sync(0xffffffffu, s1, 1);
            s1 += __shfl_xor_sync(0xffffffffu, s1, 2);
            if ((lane & 3) == 0) {
                rs[r0l][wcol] = s0;
                rs[r1l][wcol] = s1;
            }
        }
        __syncthreads();
        // coalesced att tile store: 2 threads per row, 128B each
        {
            const int r = tid >> 1;
            const int sg = (tid & 1) * 64;
            const uint4* src = (const uint4*)&smem_t[r * PT + sg];
            uint4* dst = (uint4*)&att[(size_t)(m0 + r) * S + n0 + sg];
            #pragma unroll
            for (int j = 0; j < 8; j++) dst[j] = src[j];
        }
        if (tid < 128) {
            float v = ((rs[tid][0] + rs[tid][1]) + (rs[tid][2] + rs[tid][3]));
            outf[(size_t)(m0 + tid) * 32 + (n0 >> 7)] = v;
        }
    } else {
        // out = acc * inv[row]  (bias = g_inv)
        #pragma unroll
        for (int mt = 0; mt < 4; mt++) {
            const int r0 = m0 + wm + mt * 16 + mq;
            const float i0 = bias[r0];
            const float i1 = bias[r0 + 8];
            #pragma unroll
            for (int nt = 0; nt < 4; nt++) {
                const int gn = n0 + wn + nt * 8 + nq;
                float2 p0, p1;
                p0.x = acc[mt][nt][0] * i0;  p0.y = acc[mt][nt][1] * i0;
                p1.x = acc[mt][nt][2] * i1;  p1.y = acc[mt][nt][3] * i1;
                *(float2*)&outf[(size_t)r0 * ldo + gn]       = p0;
                *(float2*)&outf[(size_t)(r0 + 8) * ldo + gn] = p1;
            }
        }
    }
}

// ---------------- rowinv: inv[i] = 1/sum(psum[i][np>>7 .. i>>7]) -------------
__global__ __launch_bounds__(256) void rowinv_kernel(
    const float* __restrict__ psum, float* __restrict__ inv,
    int S, const int* __restrict__ np_ptr)
{
    const int i = blockIdx.x * 8 + (threadIdx.x >> 5);
    const int lane = threadIdx.x & 31;
    if (i >= S) return;
    const int np = *np_ptr;
    const int lo = np >> 7;
    const int hi = i >> 7;
    float v = 0.f;
    if (i >= np && lane >= lo && lane <= hi) v = psum[(size_t)i * 32 + lane];
    #pragma unroll
    for (int off = 16; off > 0; off >>= 1) v += __shfl_xor_sync(0xffffffffu, v, off);
    if (lane == 0) inv[i] = (i >= np && v > 0.f) ? 1.f / v : 0.f;
}

// ---------------- fp32 -> fp16 (hi only) ------------------------------------
__global__ __launch_bounds__(256) void convert_h_kernel(
    const float* __restrict__ in, __half* __restrict__ h, size_t n4)
{
    for (size_t i = blockIdx.x * 256 + threadIdx.x; i < n4; i += (size_t)gridDim.x * 256) {
        float4 v = ((const float4*)in)[i];
        ((__half2*)h)[i * 2 + 0] = __half2(__float2half(v.x), __float2half(v.y));
        ((__half2*)h)[i * 2 + 1] = __half2(__float2half(v.z), __float2half(v.w));
    }
}

// ---------------- wide transpose (fp32 -> fp16): Th[c][r] = W[r][c] ---------
__global__ __launch_bounds__(256) void transpose_h_kernel(
    const float* __restrict__ W, __half* __restrict__ Th, int rows, int cols)
{
    __shared__ __half sm[64][72];
    const int bx = blockIdx.x * 64;
    const int by = blockIdx.y * 64;
    const int t  = threadIdx.x;
    const int r  = t >> 2;
    const int tg = t & 3;
    const float* src = &W[(size_t)(by + r) * cols + bx];
    #pragma unroll
    for (int j = 0; j < 4; j++) {
        const int cl = j * 16 + tg * 4;
        float4 v = *(const float4*)&src[cl];
        sm[cl + 0][r] = __float2half(v.x);
        sm[cl + 1][r] = __float2half(v.y);
        sm[cl + 2][r] = __float2half(v.z);
        sm[cl + 3][r] = __float2half(v.w);
    }
    __syncthreads();
    const int orl  = t >> 2;
    const int part = (t & 3) * 16;
    __half* dst = &Th[(size_t)(bx + orl) * rows + by + part];
    *(uint4*)&dst[0] = *(const uint4*)&sm[orl][part];
    *(uint4*)&dst[8] = *(const uint4*)&sm[orl][part + 8];
}

// ============================================================================
extern "C" void kernel_launch(void* const* d_in, const int* in_sizes, int n_in,
                              void* d_out, int out_size)
{
    const float* x  = (const float*)d_in[0];
    const float* W  = (const float*)d_in[1];
    const float* b  = (const float*)d_in[2];
    const int*   np = (const int*)  d_in[3];

    const int F3 = in_sizes[2];      // 6144
    const int F  = F3 / 3;           // 2048
    const int S  = in_sizes[0] / F;  // 4096
    float* out = (float*)d_out;

    __half *xh, *Wth, *qh, *kh, *vTh, *atth;
    float *psum, *inv;
    cudaGetSymbolAddress((void**)&xh,  g_xh);
    cudaGetSymbolAddress((void**)&Wth, g_Wth);
    cudaGetSymbolAddress((void**)&qh,  g_qh);
    cudaGetSymbolAddress((void**)&kh,  g_kh);
    cudaGetSymbolAddress((void**)&vTh, g_vTh);
    cudaGetSymbolAddress((void**)&atth, g_atth);
    cudaGetSymbolAddress((void**)&psum, g_psum);
    cudaGetSymbolAddress((void**)&inv,  g_inv);

    cudaFuncSetAttribute(hmma_gemm<0>, cudaFuncAttributeMaxDynamicSharedMemorySize, SMEM_BYTES);
    cudaFuncSetAttribute(hmma_gemm<1>, cudaFuncAttributeMaxDynamicSharedMemorySize, SMEM_BYTES);
    cudaFuncSetAttribute(hmma_gemm<2>, cudaFuncAttributeMaxDynamicSharedMemorySize, SMEM_BYTES);

    const float scale = 1.0f / sqrtf((float)F);

    convert_h_kernel<<<2048, 256>>>(x, xh, (size_t)S * F / 4);
    transpose_h_kernel<<<dim3(F3 / 64, F / 64), 256>>>(W, Wth, F, F3);

    // qkv = xh @ Wth^T + b -> q/k hi, vT hi
    hmma_gemm<0><<<dim3(F3 / 128, S / 128), 256, SMEM_BYTES>>>(
        xh, F, Wth, F, F, b, 1.0f, nullptr, 0,
        qh, kh, vTh, F, S, np);

    // scores -> att = exp(scale * q@k^T) masked, + psum (triangular 1D grid)
    const int nb = S / 128;
    hmma_gemm<1><<<nb * (nb + 1) / 2, 256, SMEM_BYTES>>>(
        qh, F, kh, F, F, nullptr, scale, psum, 0,
        atth, nullptr, nullptr, F, S, np);

    // inv[i] = 1 / rowsum
    rowinv_kernel<<<S / 8, 256>>>(psum, inv, S, np);

    // out = (att @ v) * inv[row]  (LPT reversed-y)
    hmma_gemm<2><<<dim3(F / 128, S / 128), 256, SMEM_BYTES>>>(
        atth, S, vTh, S, S, inv, 1.0f, out, F,
        nullptr, nullptr, nullptr, F, S, np);
}